// round 6
// baseline (speedup 1.0000x reference)
#include <cuda_runtime.h>
#include <cstdint>

#define D_DIM 512
#define D_VEC 128   // D_DIM / 4 (float4 stride per row)
#define MAX_NODES 100000

// Scratch (allocation-free rule: device globals are allowed)
__device__ float g_buf0[(size_t)MAX_NODES * D_DIM];
__device__ float g_buf1[(size_t)MAX_NODES * D_DIM];
__device__ int   g_rowstart[MAX_NODES + 1];

// ---------------------------------------------------------------------------
// SGEMM: C[M,512] = A[M,512] @ B[512,512], fp32
// BM=128, BN=128, BK=16, 256 threads, 8x8 micro-tile, reg-prefetch pipeline
// ---------------------------------------------------------------------------
__global__ __launch_bounds__(256) void sgemm_kernel(
    const float* __restrict__ A, const float* __restrict__ B,
    float* __restrict__ C, int M)
{
    const int K = D_DIM, N = D_DIM;
    const int BM = 128, BN = 128, BK = 16;
    __shared__ float As[BK][BM];   // transposed A tile
    __shared__ float Bs[BK][BN];

    int tid = threadIdx.x;
    int bm = blockIdx.x * BM;
    int bn = blockIdx.y * BN;

    int a_row = tid >> 2;          // 0..63 (+64 on pass 1)
    int a_col = (tid & 3) * 4;     // 0,4,8,12
    int b_row = tid >> 5;          // 0..7 (+8 on pass 1)
    int b_col = (tid & 31) * 4;

    int tx = tid % 16;             // N dir, 8 cols each
    int ty = tid / 16;             // M dir, 8 rows each

    float acc[8][8];
    #pragma unroll
    for (int i = 0; i < 8; i++)
        #pragma unroll
        for (int j = 0; j < 8; j++) acc[i][j] = 0.f;

    float4 pa[2], pb[2];

    #pragma unroll
    for (int p = 0; p < 2; p++) {
        int row = bm + a_row + p * 64;
        pa[p] = (row < M)
            ? *reinterpret_cast<const float4*>(&A[(size_t)row * K + a_col])
            : make_float4(0.f, 0.f, 0.f, 0.f);
        pb[p] = *reinterpret_cast<const float4*>(
            &B[(size_t)(b_row + p * 8) * N + bn + b_col]);
    }

    for (int k0 = 0; k0 < K; k0 += BK) {
        #pragma unroll
        for (int p = 0; p < 2; p++) {
            int ar = a_row + p * 64;
            As[a_col + 0][ar] = pa[p].x;
            As[a_col + 1][ar] = pa[p].y;
            As[a_col + 2][ar] = pa[p].z;
            As[a_col + 3][ar] = pa[p].w;
            *reinterpret_cast<float4*>(&Bs[b_row + p * 8][b_col]) = pb[p];
        }
        __syncthreads();

        int kn = k0 + BK;
        if (kn < K) {
            #pragma unroll
            for (int p = 0; p < 2; p++) {
                int row = bm + a_row + p * 64;
                pa[p] = (row < M)
                    ? *reinterpret_cast<const float4*>(&A[(size_t)row * K + kn + a_col])
                    : make_float4(0.f, 0.f, 0.f, 0.f);
                pb[p] = *reinterpret_cast<const float4*>(
                    &B[(size_t)(kn + b_row + p * 8) * N + bn + b_col]);
            }
        }

        #pragma unroll
        for (int kk = 0; kk < BK; kk++) {
            float ra[8], rb[8];
            #pragma unroll
            for (int i = 0; i < 8; i++) ra[i] = As[kk][ty * 8 + i];
            #pragma unroll
            for (int j = 0; j < 8; j++) rb[j] = Bs[kk][tx * 8 + j];
            #pragma unroll
            for (int i = 0; i < 8; i++)
                #pragma unroll
                for (int j = 0; j < 8; j++)
                    acc[i][j] += ra[i] * rb[j];
        }
        __syncthreads();
    }

    #pragma unroll
    for (int i = 0; i < 8; i++) {
        int row = bm + ty * 8 + i;
        if (row < M) {
            #pragma unroll
            for (int j = 0; j < 8; j += 4) {
                float4 v = make_float4(acc[i][j], acc[i][j+1], acc[i][j+2], acc[i][j+3]);
                *reinterpret_cast<float4*>(&C[(size_t)row * N + bn + tx * 8 + j]) = v;
            }
        }
    }
}

// ---------------------------------------------------------------------------
// Build row_start[] from sorted edge_dst via lower_bound binary search
// ---------------------------------------------------------------------------
__global__ void build_rowptr_kernel(const int* __restrict__ edge_dst,
                                    int n_edges, int n_nodes)
{
    int n = blockIdx.x * blockDim.x + threadIdx.x;
    if (n > n_nodes) return;
    int lo = 0, hi = n_edges;
    while (lo < hi) {
        int mid = (lo + hi) >> 1;
        if (edge_dst[mid] < n) lo = mid + 1; else hi = mid;
    }
    g_rowstart[n] = lo;
}

// ---------------------------------------------------------------------------
// SpMM half-hop: out[n, cols] = sum_{e in row n} w[e] * x[src[e], cols]
// Column-split so the gathered working set (102.4 MB) fits in L2 (126 MB).
//  - x rows gathered via __ldg (normal caching -> L2-resident)
//  - edge streams via __ldcs (evict-first, read once per pass)
//  - output via __stwt (write-through, no L2 pollution)
// One 64-thread block per node; float4 per thread; edge unroll x4 (MLP=4).
// ---------------------------------------------------------------------------
__global__ __launch_bounds__(64) void spmm_half_kernel(
    const float4* __restrict__ x,
    const int*    __restrict__ edge_src,
    const float*  __restrict__ edge_weight,
    float4*       __restrict__ out,
    int col_off)   // 0 or 64 (float4 units)
{
    int n = blockIdx.x;
    int c = col_off + threadIdx.x;
    int s = g_rowstart[n];
    int e = g_rowstart[n + 1];

    float4 acc = make_float4(0.f, 0.f, 0.f, 0.f);

    int i = s;
    for (; i + 4 <= e; i += 4) {
        int   s0 = __ldcs(&edge_src[i+0]);
        int   s1 = __ldcs(&edge_src[i+1]);
        int   s2 = __ldcs(&edge_src[i+2]);
        int   s3 = __ldcs(&edge_src[i+3]);
        float w0 = __ldcs(&edge_weight[i+0]);
        float w1 = __ldcs(&edge_weight[i+1]);
        float w2 = __ldcs(&edge_weight[i+2]);
        float w3 = __ldcs(&edge_weight[i+3]);
        float4 r0 = __ldg(&x[(size_t)s0 * D_VEC + c]);
        float4 r1 = __ldg(&x[(size_t)s1 * D_VEC + c]);
        float4 r2 = __ldg(&x[(size_t)s2 * D_VEC + c]);
        float4 r3 = __ldg(&x[(size_t)s3 * D_VEC + c]);
        acc.x += w0*r0.x; acc.y += w0*r0.y; acc.z += w0*r0.z; acc.w += w0*r0.w;
        acc.x += w1*r1.x; acc.y += w1*r1.y; acc.z += w1*r1.z; acc.w += w1*r1.w;
        acc.x += w2*r2.x; acc.y += w2*r2.y; acc.z += w2*r2.z; acc.w += w2*r2.w;
        acc.x += w3*r3.x; acc.y += w3*r3.y; acc.z += w3*r3.z; acc.w += w3*r3.w;
    }
    for (; i < e; i++) {
        int   sn = __ldcs(&edge_src[i]);
        float wt = __ldcs(&edge_weight[i]);
        float4 r = __ldg(&x[(size_t)sn * D_VEC + c]);
        acc.x += wt*r.x; acc.y += wt*r.y; acc.z += wt*r.z; acc.w += wt*r.w;
    }
    __stwt(&out[(size_t)n * D_VEC + c], acc);
}

static inline void spmm_hop(const float* x, const int* edge_src,
                            const float* edge_weight, float* out, int n_nodes)
{
    spmm_half_kernel<<<n_nodes, 64>>>((const float4*)x, edge_src, edge_weight,
                                      (float4*)out, 0);
    spmm_half_kernel<<<n_nodes, 64>>>((const float4*)x, edge_src, edge_weight,
                                      (float4*)out, 64);
}

// ---------------------------------------------------------------------------
// Launch
// ---------------------------------------------------------------------------
extern "C" void kernel_launch(void* const* d_in, const int* in_sizes, int n_in,
                              void* d_out, int out_size)
{
    const float* features    = (const float*)d_in[0];
    const float* weight      = (const float*)d_in[1];
    const int*   edge_src    = (const int*)  d_in[2];
    const int*   edge_dst    = (const int*)  d_in[3];
    const float* edge_weight = (const float*)d_in[4];
    // d_in[5] = times (fixed at 3); sync read forbidden under graph capture,
    // so the 3-hop sequence is unrolled below.

    int n_nodes = in_sizes[0] / D_DIM;
    int n_edges = in_sizes[2];
    float* out = (float*)d_out;

    float* buf0 = nullptr;
    float* buf1 = nullptr;
    cudaGetSymbolAddress((void**)&buf0, g_buf0);
    cudaGetSymbolAddress((void**)&buf1, g_buf1);

    // 1) support = features @ W  -> buf0
    dim3 gemm_grid((n_nodes + 127) / 128, D_DIM / 128);
    sgemm_kernel<<<gemm_grid, 256>>>(features, weight, buf0, n_nodes);

    // 2) CSR row pointers from sorted edge_dst
    build_rowptr_kernel<<<(n_nodes + 1 + 255) / 256, 256>>>(edge_dst, n_edges, n_nodes);

    // 3) three SpMM hops (each = two L2-sized column passes)
    spmm_hop(buf0, edge_src, edge_weight, buf1, n_nodes);
    spmm_hop(buf1, edge_src, edge_weight, buf0, n_nodes);
    spmm_hop(buf0, edge_src, edge_weight, out,  n_nodes);
}

// round 7
// speedup vs baseline: 1.0158x; 1.0158x over previous
#include <cuda_runtime.h>
#include <cstdint>

#define D_DIM 512
#define D_VEC 128   // D_DIM / 4 (float4 stride per row)
#define MAX_NODES 100000

// Scratch (allocation-free rule: device globals are allowed)
__device__ float g_buf0[(size_t)MAX_NODES * D_DIM];
__device__ float g_buf1[(size_t)MAX_NODES * D_DIM];
__device__ int   g_rowstart[MAX_NODES + 1];

// ---------------------------------------------------------------------------
// SGEMM: C[M,512] = A[M,512] @ B[512,512], fp32
// BM=128, BN=128, BK=16, 256 threads, 8x8 micro-tile, reg-prefetch pipeline
// ---------------------------------------------------------------------------
__global__ __launch_bounds__(256) void sgemm_kernel(
    const float* __restrict__ A, const float* __restrict__ B,
    float* __restrict__ C, int M)
{
    const int K = D_DIM, N = D_DIM;
    const int BM = 128, BN = 128, BK = 16;
    __shared__ float As[BK][BM];   // transposed A tile
    __shared__ float Bs[BK][BN];

    int tid = threadIdx.x;
    int bm = blockIdx.x * BM;
    int bn = blockIdx.y * BN;

    int a_row = tid >> 2;          // 0..63 (+64 on pass 1)
    int a_col = (tid & 3) * 4;     // 0,4,8,12
    int b_row = tid >> 5;          // 0..7 (+8 on pass 1)
    int b_col = (tid & 31) * 4;

    int tx = tid % 16;             // N dir, 8 cols each
    int ty = tid / 16;             // M dir, 8 rows each

    float acc[8][8];
    #pragma unroll
    for (int i = 0; i < 8; i++)
        #pragma unroll
        for (int j = 0; j < 8; j++) acc[i][j] = 0.f;

    float4 pa[2], pb[2];

    #pragma unroll
    for (int p = 0; p < 2; p++) {
        int row = bm + a_row + p * 64;
        pa[p] = (row < M)
            ? *reinterpret_cast<const float4*>(&A[(size_t)row * K + a_col])
            : make_float4(0.f, 0.f, 0.f, 0.f);
        pb[p] = *reinterpret_cast<const float4*>(
            &B[(size_t)(b_row + p * 8) * N + bn + b_col]);
    }

    for (int k0 = 0; k0 < K; k0 += BK) {
        #pragma unroll
        for (int p = 0; p < 2; p++) {
            int ar = a_row + p * 64;
            As[a_col + 0][ar] = pa[p].x;
            As[a_col + 1][ar] = pa[p].y;
            As[a_col + 2][ar] = pa[p].z;
            As[a_col + 3][ar] = pa[p].w;
            *reinterpret_cast<float4*>(&Bs[b_row + p * 8][b_col]) = pb[p];
        }
        __syncthreads();

        int kn = k0 + BK;
        if (kn < K) {
            #pragma unroll
            for (int p = 0; p < 2; p++) {
                int row = bm + a_row + p * 64;
                pa[p] = (row < M)
                    ? *reinterpret_cast<const float4*>(&A[(size_t)row * K + kn + a_col])
                    : make_float4(0.f, 0.f, 0.f, 0.f);
                pb[p] = *reinterpret_cast<const float4*>(
                    &B[(size_t)(kn + b_row + p * 8) * N + bn + b_col]);
            }
        }

        #pragma unroll
        for (int kk = 0; kk < BK; kk++) {
            float ra[8], rb[8];
            #pragma unroll
            for (int i = 0; i < 8; i++) ra[i] = As[kk][ty * 8 + i];
            #pragma unroll
            for (int j = 0; j < 8; j++) rb[j] = Bs[kk][tx * 8 + j];
            #pragma unroll
            for (int i = 0; i < 8; i++)
                #pragma unroll
                for (int j = 0; j < 8; j++)
                    acc[i][j] += ra[i] * rb[j];
        }
        __syncthreads();
    }

    #pragma unroll
    for (int i = 0; i < 8; i++) {
        int row = bm + ty * 8 + i;
        if (row < M) {
            #pragma unroll
            for (int j = 0; j < 8; j += 4) {
                float4 v = make_float4(acc[i][j], acc[i][j+1], acc[i][j+2], acc[i][j+3]);
                *reinterpret_cast<float4*>(&C[(size_t)row * N + bn + tx * 8 + j]) = v;
            }
        }
    }
}

// ---------------------------------------------------------------------------
// Build row_start[] from sorted edge_dst via lower_bound binary search
// ---------------------------------------------------------------------------
__global__ void build_rowptr_kernel(const int* __restrict__ edge_dst,
                                    int n_edges, int n_nodes)
{
    int n = blockIdx.x * blockDim.x + threadIdx.x;
    if (n > n_nodes) return;
    int lo = 0, hi = n_edges;
    while (lo < hi) {
        int mid = (lo + hi) >> 1;
        if (edge_dst[mid] < n) lo = mid + 1; else hi = mid;
    }
    g_rowstart[n] = lo;
}

// ---------------------------------------------------------------------------
// SpMM half-hop: out[n, cols] = sum_{e in row n} w[e] * x[src[e], cols]
// Column-split so the gathered working set (102.4 MB) fits in L2 (126 MB).
//  - x rows gathered via __ldg (normal caching -> L2-resident)
//  - edge streams via __ldcs (evict-first, read once per pass)
//  - output via __stwt (write-through, no L2 pollution)
// One 64-thread block per node; float4 per thread; edge unroll x4 (MLP=4).
// ---------------------------------------------------------------------------
__global__ __launch_bounds__(64) void spmm_half_kernel(
    const float4* __restrict__ x,
    const int*    __restrict__ edge_src,
    const float*  __restrict__ edge_weight,
    float4*       __restrict__ out,
    int col_off)   // 0 or 64 (float4 units)
{
    int n = blockIdx.x;
    int c = col_off + threadIdx.x;
    int s = g_rowstart[n];
    int e = g_rowstart[n + 1];

    float4 acc = make_float4(0.f, 0.f, 0.f, 0.f);

    int i = s;
    for (; i + 4 <= e; i += 4) {
        int   s0 = __ldcs(&edge_src[i+0]);
        int   s1 = __ldcs(&edge_src[i+1]);
        int   s2 = __ldcs(&edge_src[i+2]);
        int   s3 = __ldcs(&edge_src[i+3]);
        float w0 = __ldcs(&edge_weight[i+0]);
        float w1 = __ldcs(&edge_weight[i+1]);
        float w2 = __ldcs(&edge_weight[i+2]);
        float w3 = __ldcs(&edge_weight[i+3]);
        float4 r0 = __ldg(&x[(size_t)s0 * D_VEC + c]);
        float4 r1 = __ldg(&x[(size_t)s1 * D_VEC + c]);
        float4 r2 = __ldg(&x[(size_t)s2 * D_VEC + c]);
        float4 r3 = __ldg(&x[(size_t)s3 * D_VEC + c]);
        acc.x += w0*r0.x; acc.y += w0*r0.y; acc.z += w0*r0.z; acc.w += w0*r0.w;
        acc.x += w1*r1.x; acc.y += w1*r1.y; acc.z += w1*r1.z; acc.w += w1*r1.w;
        acc.x += w2*r2.x; acc.y += w2*r2.y; acc.z += w2*r2.z; acc.w += w2*r2.w;
        acc.x += w3*r3.x; acc.y += w3*r3.y; acc.z += w3*r3.z; acc.w += w3*r3.w;
    }
    for (; i < e; i++) {
        int   sn = __ldcs(&edge_src[i]);
        float wt = __ldcs(&edge_weight[i]);
        float4 r = __ldg(&x[(size_t)sn * D_VEC + c]);
        acc.x += wt*r.x; acc.y += wt*r.y; acc.z += wt*r.z; acc.w += wt*r.w;
    }
    __stwt(&out[(size_t)n * D_VEC + c], acc);
}

static inline void spmm_hop(const float* x, const int* edge_src,
                            const float* edge_weight, float* out, int n_nodes)
{
    spmm_half_kernel<<<n_nodes, 64>>>((const float4*)x, edge_src, edge_weight,
                                      (float4*)out, 0);
    spmm_half_kernel<<<n_nodes, 64>>>((const float4*)x, edge_src, edge_weight,
                                      (float4*)out, 64);
}

// ---------------------------------------------------------------------------
// Launch
// ---------------------------------------------------------------------------
extern "C" void kernel_launch(void* const* d_in, const int* in_sizes, int n_in,
                              void* d_out, int out_size)
{
    const float* features    = (const float*)d_in[0];
    const float* weight      = (const float*)d_in[1];
    const int*   edge_src    = (const int*)  d_in[2];
    const int*   edge_dst    = (const int*)  d_in[3];
    const float* edge_weight = (const float*)d_in[4];
    // d_in[5] = times (fixed at 3); sync read forbidden under graph capture,
    // so the 3-hop sequence is unrolled below.

    int n_nodes = in_sizes[0] / D_DIM;
    int n_edges = in_sizes[2];
    float* out = (float*)d_out;

    float* buf0 = nullptr;
    float* buf1 = nullptr;
    cudaGetSymbolAddress((void**)&buf0, g_buf0);
    cudaGetSymbolAddress((void**)&buf1, g_buf1);

    // 1) support = features @ W  -> buf0
    dim3 gemm_grid((n_nodes + 127) / 128, D_DIM / 128);
    sgemm_kernel<<<gemm_grid, 256>>>(features, weight, buf0, n_nodes);

    // 2) CSR row pointers from sorted edge_dst
    build_rowptr_kernel<<<(n_nodes + 1 + 255) / 256, 256>>>(edge_dst, n_edges, n_nodes);

    // 3) three SpMM hops (each = two L2-sized column passes)
    spmm_hop(buf0, edge_src, edge_weight, buf1, n_nodes);
    spmm_hop(buf1, edge_src, edge_weight, buf0, n_nodes);
    spmm_hop(buf0, edge_src, edge_weight, out,  n_nodes);
}

// round 9
// speedup vs baseline: 1.5016x; 1.4782x over previous
#include <cuda_runtime.h>
#include <cuda_bf16.h>
#include <cstdint>

#define D_DIM 512
#define D_VEC 128   // D_DIM / 4 (float4 stride per row)
#define MAX_NODES 100000
#define M_PAD 100096          // 782 * 128 (padded row count for GEMM tiles)
#define M_TILES 782

// ---------------------------------------------------------------------------
// Scratch (allocation-free rule: device globals are allowed)
// ---------------------------------------------------------------------------
__device__ float g_buf0[(size_t)MAX_NODES * D_DIM];
__device__ float g_buf1[(size_t)MAX_NODES * D_DIM];
__device__ int   g_rowstart[MAX_NODES + 1];
// bf16 hi/lo splits, stored as uint4 for guaranteed 16B alignment
__device__ uint4 g_ahi4[(size_t)M_PAD * 64];     // A:   [M_PAD][512] bf16
__device__ uint4 g_alo4[(size_t)M_PAD * 64];
__device__ uint4 g_bhi4[D_DIM * 64];             // W^T: [n][k] bf16
__device__ uint4 g_blo4[D_DIM * 64];

// ---------------------------------------------------------------------------
// PTX helpers (sm_103-safe: HMMA mma.sync + cp.async only, no tcgen05)
// ---------------------------------------------------------------------------
__device__ __forceinline__ uint32_t smem_to_u32(const void* p) {
    uint32_t a;
    asm("{ .reg .u64 t; cvta.to.shared.u64 t, %1; cvt.u32.u64 %0, t; }"
        : "=r"(a) : "l"(p));
    return a;
}
__device__ __forceinline__ void cp16(uint32_t s, const void* g) {
    asm volatile("cp.async.cg.shared.global [%0], [%1], 16;"
                 :: "r"(s), "l"(g) : "memory");
}
#define CP_COMMIT() asm volatile("cp.async.commit_group;" ::: "memory")
#define CP_WAIT(n)  asm volatile("cp.async.wait_group %0;" :: "n"(n) : "memory")

__device__ __forceinline__ uint32_t lds32(uint32_t a) {
    uint32_t v;
    asm("ld.shared.b32 %0, [%1];" : "=r"(v) : "r"(a));
    return v;
}
__device__ __forceinline__ void mma16816(float* d, const uint32_t* a,
                                         const uint32_t* b) {
    asm volatile(
        "mma.sync.aligned.m16n8k16.row.col.f32.bf16.bf16.f32 "
        "{%0,%1,%2,%3}, {%4,%5,%6,%7}, {%8,%9}, {%0,%1,%2,%3};"
        : "+f"(d[0]), "+f"(d[1]), "+f"(d[2]), "+f"(d[3])
        : "r"(a[0]), "r"(a[1]), "r"(a[2]), "r"(a[3]),
          "r"(b[0]), "r"(b[1]));
}

// ---------------------------------------------------------------------------
// Conversions: fp32 -> (bf16 hi, bf16 lo) splits
// ---------------------------------------------------------------------------
__global__ void convert_a_kernel(const float4* __restrict__ A, int m)
{
    size_t i = (size_t)blockIdx.x * blockDim.x + threadIdx.x;  // float4 index
    if (i >= (size_t)M_PAD * (D_DIM / 4)) return;
    size_t row = i / (D_DIM / 4);
    float4 v = make_float4(0.f, 0.f, 0.f, 0.f);
    if (row < (size_t)m) v = A[i];
    __nv_bfloat16 hx = __float2bfloat16_rn(v.x);
    __nv_bfloat16 hy = __float2bfloat16_rn(v.y);
    __nv_bfloat16 hz = __float2bfloat16_rn(v.z);
    __nv_bfloat16 hw = __float2bfloat16_rn(v.w);
    ushort4 hi, lo;
    hi.x = __bfloat16_as_ushort(hx);
    hi.y = __bfloat16_as_ushort(hy);
    hi.z = __bfloat16_as_ushort(hz);
    hi.w = __bfloat16_as_ushort(hw);
    lo.x = __bfloat16_as_ushort(__float2bfloat16_rn(v.x - __bfloat162float(hx)));
    lo.y = __bfloat16_as_ushort(__float2bfloat16_rn(v.y - __bfloat162float(hy)));
    lo.z = __bfloat16_as_ushort(__float2bfloat16_rn(v.z - __bfloat162float(hz)));
    lo.w = __bfloat16_as_ushort(__float2bfloat16_rn(v.w - __bfloat162float(hw)));
    reinterpret_cast<ushort4*>(g_ahi4)[i] = hi;
    reinterpret_cast<ushort4*>(g_alo4)[i] = lo;
}

__global__ void convert_w_kernel(const float* __restrict__ W)
{
    int i = blockIdx.x * blockDim.x + threadIdx.x;   // over k*512+n
    if (i >= D_DIM * D_DIM) return;
    int k = i / D_DIM, n = i % D_DIM;
    float w = W[i];
    __nv_bfloat16 h = __float2bfloat16_rn(w);
    __nv_bfloat16 l = __float2bfloat16_rn(w - __bfloat162float(h));
    reinterpret_cast<__nv_bfloat16*>(g_bhi4)[n * D_DIM + k] = h;
    reinterpret_cast<__nv_bfloat16*>(g_blo4)[n * D_DIM + k] = l;
}

// ---------------------------------------------------------------------------
// HMMA GEMM: C = Ahi·Bhi + Ahi·Blo + Alo·Bhi (fp32 accum)
// CTA tile 128x128, BK=32, 8 warps (2m x 4n), warp tile 64x32,
// cp.async double-buffered SMEM, 80B-padded rows (conflict-free frag LDS).
// ---------------------------------------------------------------------------
#define BK 32
#define NCHUNKS (D_DIM / BK)   // 16
#define ROWB 80                // 32 bf16 (64B) + 16B pad; (20g+tig)%32 bijective
#define MATB (128 * ROWB)      // 10240 B per matrix tile
#define AHI_OFF 0
#define ALO_OFF (1 * MATB)
#define BHI_OFF (2 * MATB)
#define BLO_OFF (3 * MATB)
#define BUFB (4 * MATB)        // 40960 B per pipeline stage
#define GEMM_SMEM (2 * BUFB)   // 81920 B

__device__ __forceinline__ void load_chunk(uint32_t buf, int bm, int bn,
                                           int kc, int tid)
{
    #pragma unroll
    for (int p = 0; p < 2; p++) {
        int u = tid + p * 256;          // 0..511
        int row = u >> 2, seg = u & 3;  // 128 rows x 4 segs (16B each)
        uint32_t so = buf + row * ROWB + seg * 16;
        size_t ga = (size_t)(bm + row) * 64 + kc * 4 + seg;
        size_t gb = (size_t)(bn + row) * 64 + kc * 4 + seg;
        cp16(so + AHI_OFF, &g_ahi4[ga]);
        cp16(so + ALO_OFF, &g_alo4[ga]);
        cp16(so + BHI_OFF, &g_bhi4[gb]);
        cp16(so + BLO_OFF, &g_blo4[gb]);
    }
}

__global__ __launch_bounds__(256, 2) void gemm_mma_kernel(
    float* __restrict__ C, int m)
{
    extern __shared__ char smem[];
    uint32_t sb = smem_to_u32(smem);
    int tid = threadIdx.x;
    int wid = tid >> 5, lane = tid & 31;
    int wm = wid & 1, wn = wid >> 1;        // warp grid 2m x 4n
    int g = lane >> 2, tig = lane & 3;
    int bn = blockIdx.x * 128;              // n fastest -> A stripe L2 reuse
    int bm = blockIdx.y * 128;

    float acc[4][4][4];
    #pragma unroll
    for (int i = 0; i < 4; i++)
        #pragma unroll
        for (int j = 0; j < 4; j++)
            #pragma unroll
            for (int r = 0; r < 4; r++) acc[i][j][r] = 0.f;

    load_chunk(sb, bm, bn, 0, tid);
    CP_COMMIT();

    for (int kc = 0; kc < NCHUNKS; kc++) {
        uint32_t cur = sb + (kc & 1) * BUFB;
        if (kc + 1 < NCHUNKS) {
            load_chunk(sb + ((kc + 1) & 1) * BUFB, bm, bn, kc + 1, tid);
            CP_COMMIT();
            CP_WAIT(1);
        } else {
            CP_WAIT(0);
        }
        __syncthreads();

        #pragma unroll
        for (int term = 0; term < 3; term++) {
            uint32_t abase = cur + (term == 2 ? ALO_OFF : AHI_OFF);
            uint32_t bbase = cur + (term == 1 ? BLO_OFF : BHI_OFF);
            #pragma unroll
            for (int ks = 0; ks < 2; ks++) {
                uint32_t kb = (uint32_t)(ks * 32 + tig * 4);
                uint32_t afr[4][4], bfr[4][2];
                #pragma unroll
                for (int mi = 0; mi < 4; mi++) {
                    uint32_t r0 = abase + (uint32_t)((wm * 64 + mi * 16 + g) * ROWB) + kb;
                    uint32_t r1 = r0 + 8 * ROWB;
                    afr[mi][0] = lds32(r0);
                    afr[mi][1] = lds32(r1);
                    afr[mi][2] = lds32(r0 + 16);
                    afr[mi][3] = lds32(r1 + 16);
                }
                #pragma unroll
                for (int nj = 0; nj < 4; nj++) {
                    uint32_t n0 = bbase + (uint32_t)((wn * 32 + nj * 8 + g) * ROWB) + kb;
                    bfr[nj][0] = lds32(n0);
                    bfr[nj][1] = lds32(n0 + 16);
                }
                #pragma unroll
                for (int mi = 0; mi < 4; mi++)
                    #pragma unroll
                    for (int nj = 0; nj < 4; nj++)
                        mma16816(acc[mi][nj], afr[mi], bfr[nj]);
            }
        }
        __syncthreads();
    }

    // Epilogue: direct float2 stores (full 32B sectors per row-quad)
    #pragma unroll
    for (int mi = 0; mi < 4; mi++) {
        int r0 = bm + wm * 64 + mi * 16 + g;
        int r1 = r0 + 8;
        #pragma unroll
        for (int nj = 0; nj < 4; nj++) {
            int col = bn + wn * 32 + nj * 8 + tig * 2;
            if (r0 < m)
                *reinterpret_cast<float2*>(&C[(size_t)r0 * D_DIM + col]) =
                    make_float2(acc[mi][nj][0], acc[mi][nj][1]);
            if (r1 < m)
                *reinterpret_cast<float2*>(&C[(size_t)r1 * D_DIM + col]) =
                    make_float2(acc[mi][nj][2], acc[mi][nj][3]);
        }
    }
}

// ---------------------------------------------------------------------------
// Build row_start[] from sorted edge_dst via lower_bound binary search
// ---------------------------------------------------------------------------
__global__ void build_rowptr_kernel(const int* __restrict__ edge_dst,
                                    int n_edges, int n_nodes)
{
    int n = blockIdx.x * blockDim.x + threadIdx.x;
    if (n > n_nodes) return;
    int lo = 0, hi = n_edges;
    while (lo < hi) {
        int mid = (lo + hi) >> 1;
        if (edge_dst[mid] < n) lo = mid + 1; else hi = mid;
    }
    g_rowstart[n] = lo;
}

// ---------------------------------------------------------------------------
// SpMM half-hop (column-split so gathered working set fits L2) — unchanged
// ---------------------------------------------------------------------------
__global__ __launch_bounds__(64) void spmm_half_kernel(
    const float4* __restrict__ x,
    const int*    __restrict__ edge_src,
    const float*  __restrict__ edge_weight,
    float4*       __restrict__ out,
    int col_off)
{
    int n = blockIdx.x;
    int c = col_off + threadIdx.x;
    int s = g_rowstart[n];
    int e = g_rowstart[n + 1];

    float4 acc = make_float4(0.f, 0.f, 0.f, 0.f);

    int i = s;
    for (; i + 4 <= e; i += 4) {
        int   s0 = __ldcs(&edge_src[i+0]);
        int   s1 = __ldcs(&edge_src[i+1]);
        int   s2 = __ldcs(&edge_src[i+2]);
        int   s3 = __ldcs(&edge_src[i+3]);
        float w0 = __ldcs(&edge_weight[i+0]);
        float w1 = __ldcs(&edge_weight[i+1]);
        float w2 = __ldcs(&edge_weight[i+2]);
        float w3 = __ldcs(&edge_weight[i+3]);
        float4 r0 = __ldg(&x[(size_t)s0 * D_VEC + c]);
        float4 r1 = __ldg(&x[(size_t)s1 * D_VEC + c]);
        float4 r2 = __ldg(&x[(size_t)s2 * D_VEC + c]);
        float4 r3 = __ldg(&x[(size_t)s3 * D_VEC + c]);
        acc.x += w0*r0.x; acc.y += w0*r0.y; acc.z += w0*r0.z; acc.w += w0*r0.w;
        acc.x += w1*r1.x; acc.y += w1*r1.y; acc.z += w1*r1.z; acc.w += w1*r1.w;
        acc.x += w2*r2.x; acc.y += w2*r2.y; acc.z += w2*r2.z; acc.w += w2*r2.w;
        acc.x += w3*r3.x; acc.y += w3*r3.y; acc.z += w3*r3.z; acc.w += w3*r3.w;
    }
    for (; i < e; i++) {
        int   sn = __ldcs(&edge_src[i]);
        float wt = __ldcs(&edge_weight[i]);
        float4 r = __ldg(&x[(size_t)sn * D_VEC + c]);
        acc.x += wt*r.x; acc.y += wt*r.y; acc.z += wt*r.z; acc.w += wt*r.w;
    }
    __stwt(&out[(size_t)n * D_VEC + c], acc);
}

static inline void spmm_hop(const float* x, const int* edge_src,
                            const float* edge_weight, float* out, int n_nodes)
{
    spmm_half_kernel<<<n_nodes, 64>>>((const float4*)x, edge_src, edge_weight,
                                      (float4*)out, 0);
    spmm_half_kernel<<<n_nodes, 64>>>((const float4*)x, edge_src, edge_weight,
                                      (float4*)out, 64);
}

// ---------------------------------------------------------------------------
// Launch
// ---------------------------------------------------------------------------
extern "C" void kernel_launch(void* const* d_in, const int* in_sizes, int n_in,
                              void* d_out, int out_size)
{
    const float* features    = (const float*)d_in[0];
    const float* weight      = (const float*)d_in[1];
    const int*   edge_src    = (const int*)  d_in[2];
    const int*   edge_dst    = (const int*)  d_in[3];
    const float* edge_weight = (const float*)d_in[4];
    // d_in[5] = times (fixed at 3); sync read forbidden under graph capture.

    int n_nodes = in_sizes[0] / D_DIM;
    int n_edges = in_sizes[2];
    float* out = (float*)d_out;

    float* buf0 = nullptr;
    float* buf1 = nullptr;
    cudaGetSymbolAddress((void**)&buf0, g_buf0);
    cudaGetSymbolAddress((void**)&buf1, g_buf1);

    cudaFuncSetAttribute(gemm_mma_kernel,
                         cudaFuncAttributeMaxDynamicSharedMemorySize, GEMM_SMEM);

    // 1) bf16 hi/lo splits of features and W^T
    {
        size_t nv = (size_t)M_PAD * (D_DIM / 4);
        convert_a_kernel<<<(unsigned)((nv + 255) / 256), 256>>>(
            (const float4*)features, n_nodes);
        convert_w_kernel<<<(D_DIM * D_DIM + 255) / 256, 256>>>(weight);
    }

    // 2) support = features @ W via HMMA (3-term bf16 split) -> buf0
    dim3 gemm_grid(D_DIM / 128, M_TILES);
    gemm_mma_kernel<<<gemm_grid, 256, GEMM_SMEM>>>(buf0, n_nodes);

    // 3) CSR row pointers from sorted edge_dst
    build_rowptr_kernel<<<(n_nodes + 1 + 255) / 256, 256>>>(edge_dst, n_edges, n_nodes);

    // 4) three SpMM hops (each = two L2-sized column passes)
    spmm_hop(buf0, edge_src, edge_weight, buf1, n_nodes);
    spmm_hop(buf1, edge_src, edge_weight, buf0, n_nodes);
    spmm_hop(buf0, edge_src, edge_weight, out,  n_nodes);
}

// round 10
// speedup vs baseline: 1.7576x; 1.1705x over previous
#include <cuda_runtime.h>
#include <cuda_bf16.h>
#include <cstdint>

#define D_DIM 512
#define D_VEC 128   // D_DIM / 4 (float4 stride per row)
#define MAX_NODES 100000
#define M_PAD 100096          // 782 * 128 (padded row count for GEMM tiles)
#define M_TILES 782

// ---------------------------------------------------------------------------
// Scratch (allocation-free rule: device globals are allowed)
// ---------------------------------------------------------------------------
__device__ float g_buf0[(size_t)MAX_NODES * D_DIM];
__device__ float g_buf1[(size_t)MAX_NODES * D_DIM];
__device__ int   g_rowstart[MAX_NODES + 1];
// bf16 hi/lo splits, stored as uint4 for guaranteed 16B alignment
__device__ uint4 g_ahi4[(size_t)M_PAD * 64];     // A:   [M_PAD][512] bf16
__device__ uint4 g_alo4[(size_t)M_PAD * 64];
__device__ uint4 g_bhi4[D_DIM * 64];             // W^T: [n][k] bf16
__device__ uint4 g_blo4[D_DIM * 64];

// ---------------------------------------------------------------------------
// PTX helpers (sm_103-safe: HMMA mma.sync + cp.async only, no tcgen05)
// ---------------------------------------------------------------------------
__device__ __forceinline__ uint32_t smem_to_u32(const void* p) {
    uint32_t a;
    asm("{ .reg .u64 t; cvta.to.shared.u64 t, %1; cvt.u32.u64 %0, t; }"
        : "=r"(a) : "l"(p));
    return a;
}
__device__ __forceinline__ void cp16(uint32_t s, const void* g) {
    asm volatile("cp.async.cg.shared.global [%0], [%1], 16;"
                 :: "r"(s), "l"(g) : "memory");
}
#define CP_COMMIT() asm volatile("cp.async.commit_group;" ::: "memory")
#define CP_WAIT(n)  asm volatile("cp.async.wait_group %0;" :: "n"(n) : "memory")

__device__ __forceinline__ uint32_t lds32(uint32_t a) {
    uint32_t v;
    asm("ld.shared.b32 %0, [%1];" : "=r"(v) : "r"(a));
    return v;
}
__device__ __forceinline__ void mma16816(float* d, const uint32_t* a,
                                         const uint32_t* b) {
    asm volatile(
        "mma.sync.aligned.m16n8k16.row.col.f32.bf16.bf16.f32 "
        "{%0,%1,%2,%3}, {%4,%5,%6,%7}, {%8,%9}, {%0,%1,%2,%3};"
        : "+f"(d[0]), "+f"(d[1]), "+f"(d[2]), "+f"(d[3])
        : "r"(a[0]), "r"(a[1]), "r"(a[2]), "r"(a[3]),
          "r"(b[0]), "r"(b[1]));
}

// ---------------------------------------------------------------------------
// Conversions: fp32 -> (bf16 hi, bf16 lo) splits
// ---------------------------------------------------------------------------
__global__ void convert_a_kernel(const float4* __restrict__ A, int m)
{
    size_t i = (size_t)blockIdx.x * blockDim.x + threadIdx.x;  // float4 index
    if (i >= (size_t)M_PAD * (D_DIM / 4)) return;
    size_t row = i / (D_DIM / 4);
    float4 v = make_float4(0.f, 0.f, 0.f, 0.f);
    if (row < (size_t)m) v = A[i];
    __nv_bfloat16 hx = __float2bfloat16_rn(v.x);
    __nv_bfloat16 hy = __float2bfloat16_rn(v.y);
    __nv_bfloat16 hz = __float2bfloat16_rn(v.z);
    __nv_bfloat16 hw = __float2bfloat16_rn(v.w);
    ushort4 hi, lo;
    hi.x = __bfloat16_as_ushort(hx);
    hi.y = __bfloat16_as_ushort(hy);
    hi.z = __bfloat16_as_ushort(hz);
    hi.w = __bfloat16_as_ushort(hw);
    lo.x = __bfloat16_as_ushort(__float2bfloat16_rn(v.x - __bfloat162float(hx)));
    lo.y = __bfloat16_as_ushort(__float2bfloat16_rn(v.y - __bfloat162float(hy)));
    lo.z = __bfloat16_as_ushort(__float2bfloat16_rn(v.z - __bfloat162float(hz)));
    lo.w = __bfloat16_as_ushort(__float2bfloat16_rn(v.w - __bfloat162float(hw)));
    reinterpret_cast<ushort4*>(g_ahi4)[i] = hi;
    reinterpret_cast<ushort4*>(g_alo4)[i] = lo;
}

__global__ void convert_w_kernel(const float* __restrict__ W)
{
    int i = blockIdx.x * blockDim.x + threadIdx.x;   // over k*512+n
    if (i >= D_DIM * D_DIM) return;
    int k = i / D_DIM, n = i % D_DIM;
    float w = W[i];
    __nv_bfloat16 h = __float2bfloat16_rn(w);
    __nv_bfloat16 l = __float2bfloat16_rn(w - __bfloat162float(h));
    reinterpret_cast<__nv_bfloat16*>(g_bhi4)[n * D_DIM + k] = h;
    reinterpret_cast<__nv_bfloat16*>(g_blo4)[n * D_DIM + k] = l;
}

// ---------------------------------------------------------------------------
// HMMA GEMM: C = Ahi·Bhi + Ahi·Blo + Alo·Bhi (fp32 accum) — unchanged from R9
// ---------------------------------------------------------------------------
#define BK 32
#define NCHUNKS (D_DIM / BK)   // 16
#define ROWB 80                // 32 bf16 (64B) + 16B pad
#define MATB (128 * ROWB)
#define AHI_OFF 0
#define ALO_OFF (1 * MATB)
#define BHI_OFF (2 * MATB)
#define BLO_OFF (3 * MATB)
#define BUFB (4 * MATB)
#define GEMM_SMEM (2 * BUFB)   // 81920 B

__device__ __forceinline__ void load_chunk(uint32_t buf, int bm, int bn,
                                           int kc, int tid)
{
    #pragma unroll
    for (int p = 0; p < 2; p++) {
        int u = tid + p * 256;
        int row = u >> 2, seg = u & 3;
        uint32_t so = buf + row * ROWB + seg * 16;
        size_t ga = (size_t)(bm + row) * 64 + kc * 4 + seg;
        size_t gb = (size_t)(bn + row) * 64 + kc * 4 + seg;
        cp16(so + AHI_OFF, &g_ahi4[ga]);
        cp16(so + ALO_OFF, &g_alo4[ga]);
        cp16(so + BHI_OFF, &g_bhi4[gb]);
        cp16(so + BLO_OFF, &g_blo4[gb]);
    }
}

__global__ __launch_bounds__(256, 2) void gemm_mma_kernel(
    float* __restrict__ C, int m)
{
    extern __shared__ char smem[];
    uint32_t sb = smem_to_u32(smem);
    int tid = threadIdx.x;
    int wid = tid >> 5, lane = tid & 31;
    int wm = wid & 1, wn = wid >> 1;
    int g = lane >> 2, tig = lane & 3;
    int bn = blockIdx.x * 128;
    int bm = blockIdx.y * 128;

    float acc[4][4][4];
    #pragma unroll
    for (int i = 0; i < 4; i++)
        #pragma unroll
        for (int j = 0; j < 4; j++)
            #pragma unroll
            for (int r = 0; r < 4; r++) acc[i][j][r] = 0.f;

    load_chunk(sb, bm, bn, 0, tid);
    CP_COMMIT();

    for (int kc = 0; kc < NCHUNKS; kc++) {
        uint32_t cur = sb + (kc & 1) * BUFB;
        if (kc + 1 < NCHUNKS) {
            load_chunk(sb + ((kc + 1) & 1) * BUFB, bm, bn, kc + 1, tid);
            CP_COMMIT();
            CP_WAIT(1);
        } else {
            CP_WAIT(0);
        }
        __syncthreads();

        #pragma unroll
        for (int term = 0; term < 3; term++) {
            uint32_t abase = cur + (term == 2 ? ALO_OFF : AHI_OFF);
            uint32_t bbase = cur + (term == 1 ? BLO_OFF : BHI_OFF);
            #pragma unroll
            for (int ks = 0; ks < 2; ks++) {
                uint32_t kb = (uint32_t)(ks * 32 + tig * 4);
                uint32_t afr[4][4], bfr[4][2];
                #pragma unroll
                for (int mi = 0; mi < 4; mi++) {
                    uint32_t r0 = abase + (uint32_t)((wm * 64 + mi * 16 + g) * ROWB) + kb;
                    uint32_t r1 = r0 + 8 * ROWB;
                    afr[mi][0] = lds32(r0);
                    afr[mi][1] = lds32(r1);
                    afr[mi][2] = lds32(r0 + 16);
                    afr[mi][3] = lds32(r1 + 16);
                }
                #pragma unroll
                for (int nj = 0; nj < 4; nj++) {
                    uint32_t n0 = bbase + (uint32_t)((wn * 32 + nj * 8 + g) * ROWB) + kb;
                    bfr[nj][0] = lds32(n0);
                    bfr[nj][1] = lds32(n0 + 16);
                }
                #pragma unroll
                for (int mi = 0; mi < 4; mi++)
                    #pragma unroll
                    for (int nj = 0; nj < 4; nj++)
                        mma16816(acc[mi][nj], afr[mi], bfr[nj]);
            }
        }
        __syncthreads();
    }

    #pragma unroll
    for (int mi = 0; mi < 4; mi++) {
        int r0 = bm + wm * 64 + mi * 16 + g;
        int r1 = r0 + 8;
        #pragma unroll
        for (int nj = 0; nj < 4; nj++) {
            int col = bn + wn * 32 + nj * 8 + tig * 2;
            if (r0 < m)
                *reinterpret_cast<float2*>(&C[(size_t)r0 * D_DIM + col]) =
                    make_float2(acc[mi][nj][0], acc[mi][nj][1]);
            if (r1 < m)
                *reinterpret_cast<float2*>(&C[(size_t)r1 * D_DIM + col]) =
                    make_float2(acc[mi][nj][2], acc[mi][nj][3]);
        }
    }
}

// ---------------------------------------------------------------------------
// Build row_start[] from sorted edge_dst via lower_bound binary search
// ---------------------------------------------------------------------------
__global__ void build_rowptr_kernel(const int* __restrict__ edge_dst,
                                    int n_edges, int n_nodes)
{
    int n = blockIdx.x * blockDim.x + threadIdx.x;
    if (n > n_nodes) return;
    int lo = 0, hi = n_edges;
    while (lo < hi) {
        int mid = (lo + hi) >> 1;
        if (edge_dst[mid] < n) lo = mid + 1; else hi = mid;
    }
    g_rowstart[n] = lo;
}

// ---------------------------------------------------------------------------
// SpMM quarter-column kernel: one warp per destination node, 32 float4 cols.
// Gather unroll x8 (MLP=8) + x4 middle + scalar tail.
// FINAL hop stores __stwt (bypass L2); intermediate hops store default
// (write-back -> stays L2-resident for the NEXT hop's gather).
// ---------------------------------------------------------------------------
template <int FINAL>
__global__ __launch_bounds__(64) void spmm_q_kernel(
    const float4* __restrict__ x,
    const int*    __restrict__ edge_src,
    const float*  __restrict__ edge_weight,
    float4*       __restrict__ out,
    int col_off,     // float4 units: 0,32,64,96
    int n_nodes)
{
    int warp = threadIdx.x >> 5;
    int n = blockIdx.x * 2 + warp;
    if (n >= n_nodes) return;
    int lane = threadIdx.x & 31;
    int c = col_off + lane;
    int s = g_rowstart[n];
    int e = g_rowstart[n + 1];

    float4 acc = make_float4(0.f, 0.f, 0.f, 0.f);

    int i = s;
    for (; i + 8 <= e; i += 8) {
        int   si[8];
        float w[8];
        float4 r[8];
        #pragma unroll
        for (int j = 0; j < 8; j++) {
            si[j] = __ldcs(&edge_src[i + j]);
            w[j]  = __ldcs(&edge_weight[i + j]);
        }
        #pragma unroll
        for (int j = 0; j < 8; j++)
            r[j] = __ldg(&x[(size_t)si[j] * D_VEC + c]);
        #pragma unroll
        for (int j = 0; j < 8; j++) {
            acc.x += w[j] * r[j].x;
            acc.y += w[j] * r[j].y;
            acc.z += w[j] * r[j].z;
            acc.w += w[j] * r[j].w;
        }
    }
    if (i + 4 <= e) {
        int   si[4];
        float w[4];
        float4 r[4];
        #pragma unroll
        for (int j = 0; j < 4; j++) {
            si[j] = __ldcs(&edge_src[i + j]);
            w[j]  = __ldcs(&edge_weight[i + j]);
        }
        #pragma unroll
        for (int j = 0; j < 4; j++)
            r[j] = __ldg(&x[(size_t)si[j] * D_VEC + c]);
        #pragma unroll
        for (int j = 0; j < 4; j++) {
            acc.x += w[j] * r[j].x;
            acc.y += w[j] * r[j].y;
            acc.z += w[j] * r[j].z;
            acc.w += w[j] * r[j].w;
        }
        i += 4;
    }
    for (; i < e; i++) {
        int   sn = __ldcs(&edge_src[i]);
        float wt = __ldcs(&edge_weight[i]);
        float4 r = __ldg(&x[(size_t)sn * D_VEC + c]);
        acc.x += wt * r.x;
        acc.y += wt * r.y;
        acc.z += wt * r.z;
        acc.w += wt * r.w;
    }

    if (FINAL)
        __stwt(&out[(size_t)n * D_VEC + c], acc);
    else
        out[(size_t)n * D_VEC + c] = acc;
}

// ---------------------------------------------------------------------------
// Launch
// ---------------------------------------------------------------------------
extern "C" void kernel_launch(void* const* d_in, const int* in_sizes, int n_in,
                              void* d_out, int out_size)
{
    const float* features    = (const float*)d_in[0];
    const float* weight      = (const float*)d_in[1];
    const int*   edge_src    = (const int*)  d_in[2];
    const int*   edge_dst    = (const int*)  d_in[3];
    const float* edge_weight = (const float*)d_in[4];
    // d_in[5] = times (fixed at 3); sync read forbidden under graph capture.

    int n_nodes = in_sizes[0] / D_DIM;
    int n_edges = in_sizes[2];
    float* out = (float*)d_out;

    float* buf0 = nullptr;
    float* buf1 = nullptr;
    cudaGetSymbolAddress((void**)&buf0, g_buf0);
    cudaGetSymbolAddress((void**)&buf1, g_buf1);

    cudaFuncSetAttribute(gemm_mma_kernel,
                         cudaFuncAttributeMaxDynamicSharedMemorySize, GEMM_SMEM);

    // 1) bf16 hi/lo splits of features and W^T
    {
        size_t nv = (size_t)M_PAD * (D_DIM / 4);
        convert_a_kernel<<<(unsigned)((nv + 255) / 256), 256>>>(
            (const float4*)features, n_nodes);
        convert_w_kernel<<<(D_DIM * D_DIM + 255) / 256, 256>>>(weight);
    }

    // 2) support = features @ W via HMMA (3-term bf16 split) -> buf0
    dim3 gemm_grid(D_DIM / 128, M_TILES);
    gemm_mma_kernel<<<gemm_grid, 256, GEMM_SMEM>>>(buf0, n_nodes);

    // 3) CSR row pointers from sorted edge_dst
    build_rowptr_kernel<<<(n_nodes + 1 + 255) / 256, 256>>>(edge_dst, n_edges, n_nodes);

    // 4) 3-hop chain per column quarter (51 MB slices -> L2-resident chaining)
    int spmm_grid = (n_nodes + 1) / 2;
    for (int q = 0; q < 4; q++) {
        int co = q * 32;   // float4 column offset
        spmm_q_kernel<0><<<spmm_grid, 64>>>((const float4*)buf0, edge_src,
                                            edge_weight, (float4*)buf1, co, n_nodes);
        spmm_q_kernel<0><<<spmm_grid, 64>>>((const float4*)buf1, edge_src,
                                            edge_weight, (float4*)buf0, co, n_nodes);
        spmm_q_kernel<1><<<spmm_grid, 64>>>((const float4*)buf0, edge_src,
                                            edge_weight, (float4*)out, co, n_nodes);
    }
}